// round 4
// baseline (speedup 1.0000x reference)
#include <cuda_runtime.h>
#include <cuda_bf16.h>

// LineRaster2d: canvas[x][y] = max(LINE_WIDTH - dist(point, segment), 0) if dist < LINE_WIDTH else 0
// H = W = 6144, LINE_WIDTH = 1.0
// Output: 6144*6144 fp32 = 151 MB -> pure store-bandwidth bound.

#define H 6144
#define W 6144

// W/4 float4 per row
#define W4 (W / 4)          // 1536
#define TOTAL4 (H * W4)     // 9,437,184 float4 stores

__global__ void __launch_bounds__(256) line_raster_kernel(
    const float* __restrict__ p0_in,
    const float* __restrict__ p1_in,
    float* __restrict__ out)
{
    int idx = blockIdx.x * blockDim.x + threadIdx.x;
    if (idx >= TOTAL4) return;

    // Segment constants (4 scalar loads, L1/const-path broadcast; negligible)
    float p0x = __ldg(&p0_in[0]) * (float)H;
    float p0y = __ldg(&p0_in[1]) * (float)W;
    float p1x = __ldg(&p1_in[0]) * (float)H;
    float p1y = __ldg(&p1_in[1]) * (float)W;

    float dx = p1x - p0x;
    float dy = p1y - p0y;
    float len_sq = dx * dx + dy * dy;
    float inv_len = 1.0f / len_sq;   // random points: len_sq > 0

    int x  = idx / W4;
    int y0 = (idx - x * W4) * 4;

    float X  = (float)x;
    float px = X - p0x;

    // dot at y0, incremented by dy per y-step
    float py0 = (float)y0 - p0y;
    float dot = px * dx + py0 * dy;

    float4 v;
    float* vp = &v.x;

    #pragma unroll
    for (int j = 0; j < 4; j++) {
        float Y = (float)(y0 + j);
        float t = dot * inv_len;
        t = fminf(fmaxf(t, 0.0f), 1.0f);
        float projx = fmaf(t, dx, p0x);
        float projy = fmaf(t, dy, p0y);
        float ex = X - projx;
        float ey = Y - projy;
        float dist_sq = ex * ex + ey * ey;
        float val = 0.0f;
        if (dist_sq < 1.0f) {                 // LINE_WIDTH^2 == 1
            val = 1.0f - sqrtf(dist_sq);      // rare path: MUFU only near the line
        }
        vp[j] = val;
        dot += dy;
    }

    reinterpret_cast<float4*>(out)[idx] = v;
}

extern "C" void kernel_launch(void* const* d_in, const int* in_sizes, int n_in,
                              void* d_out, int out_size) {
    const float* p0 = (const float*)d_in[0];
    const float* p1 = (const float*)d_in[1];
    float* out = (float*)d_out;

    const int threads = 256;
    const int blocks = (TOTAL4 + threads - 1) / threads;  // 36864
    line_raster_kernel<<<blocks, threads>>>(p0, p1, out);
}

// round 6
// speedup vs baseline: 1.2512x; 1.2512x over previous
#include <cuda_runtime.h>
#include <cuda_bf16.h>

// LineRaster2d: canvas[x][y] = LINE_WIDTH - dist if dist(point,segment) < LINE_WIDTH else 0
// H = W = 6144, LINE_WIDTH = 1.0
//
// Split strategy: >99.9% of pixels are zero. Kernel 1 zero-fills at pure store
// bandwidth (no per-pixel math). Kernel 2 evaluates the exact formula only in a
// conservative band around the segment (one warp per row).

#define H 6144
#define W 6144

#define W4     (W / 4)        // 1536 float4 per row
#define TOTAL4 (H * W4)       // 9,437,184 float4
#define FILL_STORES_PER_THREAD 4
#define FILL_THREADS (TOTAL4 / FILL_STORES_PER_THREAD)  // 2,359,296 (exact)

// ---------------------------------------------------------------------------
// Kernel 1: zero fill. Each thread does 4 fully-coalesced STG.128 at stride
// FILL_THREADS so every instruction covers contiguous 128B-aligned lines.
// No per-pixel math -> store-pipe bound.
// ---------------------------------------------------------------------------
__global__ void __launch_bounds__(256) fill_zero_kernel(float4* __restrict__ out)
{
    int i = blockIdx.x * blockDim.x + threadIdx.x;
    const float4 z = make_float4(0.f, 0.f, 0.f, 0.f);
    out[i]                    = z;
    out[i +     FILL_THREADS] = z;
    out[i + 2 * FILL_THREADS] = z;
    out[i + 3 * FILL_THREADS] = z;
}

// ---------------------------------------------------------------------------
// Kernel 2: band rasterizer. One warp per row X. Computes a conservative
// y-interval that can contain dist<1 pixels, then lanes evaluate exactly.
//
// Correctness of the interval: if pixel (X,y) has dist<1, its nearest segment
// point s=(sx,sy) satisfies |X-sx| <= dist < 1 and |y-sy| <= dist < 1. So s
// lies on the sub-segment with sx in (X-1, X+1) (t-range [tlo,thi] below), and
// y lies within 1 of that sub-segment's y-range.
// ---------------------------------------------------------------------------
__global__ void __launch_bounds__(256) band_kernel(
    const float* __restrict__ p0_in,
    const float* __restrict__ p1_in,
    float* __restrict__ out)
{
    int warp_id = (blockIdx.x * blockDim.x + threadIdx.x) >> 5;
    int lane    = threadIdx.x & 31;
    if (warp_id >= H) return;

    float p0x = p0_in[0] * (float)H;
    float p0y = p0_in[1] * (float)W;
    float p1x = p1_in[0] * (float)H;
    float p1y = p1_in[1] * (float)W;

    float dx = p1x - p0x;
    float dy = p1y - p0y;
    float len_sq  = dx * dx + dy * dy;
    float inv_len = 1.0f / len_sq;

    float X = (float)warp_id;

    // t-range of the sub-segment whose x lies in [X-1, X+1], clamped to [0,1]
    float tlo, thi;
    if (fabsf(dx) > 1e-12f) {
        float ta = (X - 1.0f - p0x) / dx;
        float tb = (X + 1.0f - p0x) / dx;
        tlo = fminf(ta, tb);
        thi = fmaxf(ta, tb);
        tlo = fmaxf(tlo, 0.0f);
        thi = fminf(thi, 1.0f);
        if (tlo > thi) return;   // segment never comes within 1 in x of this row
    } else {
        if (fabsf(X - p0x) >= 1.0f) return;
        tlo = 0.0f; thi = 1.0f;
    }

    // y-range of that sub-segment, expanded by 1 (band half-width)
    float ya = fmaf(tlo, dy, p0y);
    float yb = fmaf(thi, dy, p0y);
    float ylo = fminf(ya, yb) - 1.0f;
    float yhi = fmaxf(ya, yb) + 1.0f;

    int iy0 = max(0,     (int)floorf(ylo));
    int iy1 = min(W - 1, (int)ceilf(yhi));

    float px  = X - p0x;
    float pxd = px * dx;           // constant part of the dot product

    long long row_base = (long long)warp_id * W;

    for (int y = iy0 + lane; y <= iy1; y += 32) {
        float Y  = (float)y;
        float py = Y - p0y;
        float t  = (pxd + py * dy) * inv_len;
        t = fminf(fmaxf(t, 0.0f), 1.0f);
        float projx = fmaf(t, dx, p0x);
        float projy = fmaf(t, dy, p0y);
        float ex = X - projx;
        float ey = Y - projy;
        float dist_sq = ex * ex + ey * ey;
        if (dist_sq < 1.0f) {
            out[row_base + y] = 1.0f - sqrtf(dist_sq);
        }
    }
}

extern "C" void kernel_launch(void* const* d_in, const int* in_sizes, int n_in,
                              void* d_out, int out_size) {
    (void)in_sizes; (void)n_in; (void)out_size;
    const float* p0 = (const float*)d_in[0];
    const float* p1 = (const float*)d_in[1];
    float* out = (float*)d_out;

    // 1) zero-fill at store bandwidth
    fill_zero_kernel<<<FILL_THREADS / 256, 256>>>((float4*)out);

    // 2) exact evaluation only inside the band (one warp per row)
    const int warps_per_block = 256 / 32;                    // 8
    const int blocks = (H + warps_per_block - 1) / warps_per_block;  // 768
    band_kernel<<<blocks, 256>>>(p0, p1, out);
}

// round 7
// speedup vs baseline: 1.3550x; 1.0830x over previous
#include <cuda_runtime.h>
#include <cuda_bf16.h>

// LineRaster2d: canvas[x][y] = LINE_WIDTH - dist if dist(point,segment) < LINE_WIDTH else 0
// H = W = 6144, LINE_WIDTH = 1.0
//
// Single fused kernel: one block per row. Each thread computes the row's
// conservative non-zero band interval (cheap, amortized over 16 pixels), then
// stores zeros via coalesced STG.128 for the >99.9% of spans outside the band,
// and evaluates the exact formula only inside it. Store-bandwidth bound.

#define H 6144
#define W 6144
#define ROW_F4 (W / 4)          // 1536 float4 per row
#define TPB    384              // threads per block; 4 float4 per thread

__global__ void __launch_bounds__(TPB) raster_fused_kernel(
    const float* __restrict__ p0_in,
    const float* __restrict__ p1_in,
    float4* __restrict__ out)
{
    const int x = blockIdx.x;           // row
    const int t = threadIdx.x;

    // Segment constants (broadcast loads)
    float p0x = p0_in[0] * (float)H;
    float p0y = p0_in[1] * (float)W;
    float p1x = p1_in[0] * (float)H;
    float p1y = p1_in[1] * (float)W;

    float dx = p1x - p0x;
    float dy = p1y - p0y;
    float len_sq  = dx * dx + dy * dy;
    float inv_len = 1.0f / len_sq;

    float X = (float)x;

    // Conservative band for this row: any pixel (X,y) with dist<1 has its
    // nearest segment point s with |X-sx|<1 and |y-sy|<1. Restrict the segment
    // to sx in (X-1, X+1) -> t-range [tlo,thi]; nonzero y lies within 1 of that
    // sub-segment's y-extent.
    bool has_band;
    float ylo = 0.0f, yhi = -1.0f;
    {
        float tlo, thi;
        if (fabsf(dx) > 1e-12f) {
            float ta = (X - 1.0f - p0x) / dx;
            float tb = (X + 1.0f - p0x) / dx;
            tlo = fmaxf(fminf(ta, tb), 0.0f);
            thi = fminf(fmaxf(ta, tb), 1.0f);
            has_band = (tlo <= thi);
        } else {
            has_band = (fabsf(X - p0x) < 1.0f);
            tlo = 0.0f; thi = 1.0f;
        }
        if (has_band) {
            float ya = fmaf(tlo, dy, p0y);
            float yb = fmaf(thi, dy, p0y);
            ylo = fminf(ya, yb) - 1.0f;
            yhi = fmaxf(ya, yb) + 1.0f;
        }
    }

    float px  = X - p0x;
    float pxd = px * dx;                      // constant part of dot product

    float4* __restrict__ row = out + (size_t)x * ROW_F4;

    #pragma unroll
    for (int s = 0; s < 4; s++) {
        int   f4 = t + s * TPB;               // float4 index within row
        float a  = (float)(f4 << 2);          // first y of this 4-pixel span

        float4 v = make_float4(0.f, 0.f, 0.f, 0.f);

        // Span [a, a+3] can only hold non-zeros if it meets [ylo, yhi].
        if (has_band && (yhi >= a) && (ylo <= a + 3.0f)) {
            float* vp = &v.x;
            #pragma unroll
            for (int j = 0; j < 4; j++) {
                float Y  = a + (float)j;
                float py = Y - p0y;
                float tt = (pxd + py * dy) * inv_len;
                tt = fminf(fmaxf(tt, 0.0f), 1.0f);
                float projx = fmaf(tt, dx, p0x);
                float projy = fmaf(tt, dy, p0y);
                float ex = X - projx;
                float ey = Y - projy;
                float dist_sq = ex * ex + ey * ey;
                if (dist_sq < 1.0f) {
                    vp[j] = 1.0f - sqrtf(dist_sq);
                }
            }
        }

        row[f4] = v;                          // coalesced STG.128
    }
}

extern "C" void kernel_launch(void* const* d_in, const int* in_sizes, int n_in,
                              void* d_out, int out_size) {
    (void)in_sizes; (void)n_in; (void)out_size;
    const float* p0 = (const float*)d_in[0];
    const float* p1 = (const float*)d_in[1];
    float4* out = (float4*)d_out;

    raster_fused_kernel<<<H, TPB>>>(p0, p1, out);
}